// round 11
// baseline (speedup 1.0000x reference)
#include <cuda_runtime.h>
#include <math.h>
#include <stdint.h>

#define T_LEN 200
#define E_DIM 64
#define H1 80
#define H2 40
#define NTHREADS 512
#define NSTRIPES 13        // 208 rows = 13 * 16 (covers T=200)
#define ROWS (16 * NSTRIPES)

#define FS 68              // facts tile stride [208][68]; float4-granule conflict-free
#define FSH_ELEMS (ROWS * FS)

__device__ __forceinline__ float sigm(float x) {
    float t;
    asm("tanh.approx.f32 %0, %1;" : "=f"(t) : "f"(0.5f * x));
    return fmaf(0.5f, t, 0.5f);
}
__device__ __forceinline__ void mma_tf32(float c[4], const uint32_t a[4], const uint32_t b[2]) {
    asm volatile(
        "mma.sync.aligned.m16n8k8.row.col.f32.tf32.tf32.f32 "
        "{%0,%1,%2,%3}, {%4,%5,%6,%7}, {%8,%9}, {%0,%1,%2,%3};"
        : "+f"(c[0]), "+f"(c[1]), "+f"(c[2]), "+f"(c[3])
        : "r"(a[0]), "r"(a[1]), "r"(a[2]), "r"(a[3]), "r"(b[0]), "r"(b[1]));
}
__device__ __forceinline__ void cp_async16(uint32_t smem_addr, const void* gptr) {
    asm volatile("cp.async.cg.shared.global [%0], [%1], 16;" :: "r"(smem_addr), "l"(gptr));
}

// ============================================================================
// Persistent fused kernel: one 512-thread CTA per SM loops over batches with
// double-buffered cp.async facts prefetch. Per batch: wfr transform (L2),
// tensor-core MLP (1 stripe / warp), masked softmax, attn-weighted sum.
// ============================================================================
__global__ __launch_bounds__(NTHREADS, 1)
void persistent_kernel(const float* __restrict__ query,
                       const float* __restrict__ facts,
                       const int*   __restrict__ mask,
                       const float* __restrict__ W1,
                       const float* __restrict__ b1,
                       const float* __restrict__ W2,
                       const float* __restrict__ b2,
                       const float* __restrict__ W3,
                       float* __restrict__ out,
                       int B)
{
    extern __shared__ float sm[];
    float* fsh0    = sm;                   // [208][68] buffer 0
    float* fsh1    = fsh0 + FSH_ELEMS;     // [208][68] buffer 1
    float* wfr     = fsh1 + FSH_ELEMS;     // [5120] fragment-packed wefft (perm cols)
    float* w2fr    = wfr + 5120;           // [3200] fragment-packed W2
    float* c1sh    = w2fr + 3200;          // [80]
    float* c1p     = c1sh + H1;            // [320] c1 partials (4 chunks x 80)
    float* b2sh    = c1p + 320;            // [40]
    float* w3sh    = b2sh + H2;            // [40]
    float* scoresh = w3sh + H2;            // [208]
    float* red     = scoresh + ROWS;       // [32]
    float* attnsh  = red + 32;             // [208]
    float* outred  = attnsh + ROWS;        // [512]
    float* qsh     = outred + NTHREADS;    // [64]

    const int tid  = threadIdx.x;
    const int w    = tid >> 5;
    const int lane = tid & 31;
    const int g    = lane >> 2;
    const int tg   = lane & 3;

    uint32_t fsh_base[2];
    asm("{ .reg .u64 t; cvta.to.shared.u64 t, %1; cvt.u32.u64 %0, t; }"
        : "=r"(fsh_base[0]) : "l"(fsh0));
    asm("{ .reg .u64 t; cvta.to.shared.u64 t, %1; cvt.u32.u64 %0, t; }"
        : "=r"(fsh_base[1]) : "l"(fsh1));

    // ---------------- prologue (once per CTA) ----------------
    if (tid < H2) { b2sh[tid] = b2[tid]; w3sh[tid] = W3[tid]; }
    // W2 fragments (identity k-order)
    for (int fp = tid; fp < 1600; fp += NTHREADS) {
        int kt = fp / 160, rem = fp - kt * 160;
        int j = rem >> 5, l5 = rem & 31;
        int gg = l5 >> 2, tt = l5 & 3;
        int n = j * 8 + gg;
        int ka = kt * 8 + tt;
        *(float2*)&w2fr[2 * fp] = make_float2(W2[ka * H2 + n], W2[(ka + 4) * H2 + n]);
    }
    // zero pad rows [200,208) of BOTH facts buffers (never overwritten by prefetch)
    for (int i = tid; i < (ROWS - T_LEN) * 16; i += NTHREADS) {
        int t = T_LEN + (i >> 4), e4 = i & 15;
        *(float4*)&fsh0[t * FS + e4 * 4] = make_float4(0.f, 0.f, 0.f, 0.f);
        *(float4*)&fsh1[t * FS + e4 * 4] = make_float4(0.f, 0.f, 0.f, 0.f);
    }
    // prefetch first batch into buffer 0
    {
        int b0 = blockIdx.x;
        if (b0 < B) {
            const float4* fb = (const float4*)(facts + (size_t)b0 * T_LEN * E_DIM);
            for (int i = tid; i < T_LEN * 16; i += NTHREADS) {
                int t = i >> 4, e4 = i & 15;
                cp_async16(fsh_base[0] + (t * FS + e4 * 4) * 4, fb + i);
            }
        }
        asm volatile("cp.async.commit_group;");
    }

    int parity = 0;
    for (int bi = blockIdx.x; bi < B; bi += gridDim.x, parity ^= 1) {
        const int nxt = bi + gridDim.x;

        // ---- A: prefetch next batch into the other buffer ----
        if (nxt < B) {
            const float4* fb = (const float4*)(facts + (size_t)nxt * T_LEN * E_DIM);
            const uint32_t dstb = fsh_base[parity ^ 1];
            for (int i = tid; i < T_LEN * 16; i += NTHREADS) {
                int t = i >> 4, e4 = i & 15;
                cp_async16(dstb + (t * FS + e4 * 4) * 4, fb + i);
            }
        }
        asm volatile("cp.async.commit_group;");   // empty group on last iter keeps accounting exact

        // ---- B: per-batch scalars ----
        if (tid < E_DIM) qsh[tid] = query[(size_t)bi * E_DIM + tid];
        int mbit = (tid < T_LEN) ? mask[(size_t)bi * T_LEN + tid] : 0;
        __syncthreads();    // qsh visible

        // ---- C: wfr (permuted fragment packing) + c1 partials, from L2 W1 ----
        for (int fp = tid; fp < 2560; fp += NTHREADS) {
            int kt = fp / 320, rem = fp - kt * 320;
            int j = rem >> 5, l5 = rem & 31;
            int gg = l5 >> 2, tt = l5 & 3;
            int n = j * 8 + ((gg >> 1) + (gg & 1) * 4);   // perm: C-frag == GEMM2 A-frag
            int ka = kt * 8 + tt, kb = ka + 4;
            float va = W1[(64 + ka) * H1 + n] - W1[(128 + ka) * H1 + n] + qsh[ka] * W1[(192 + ka) * H1 + n];
            float vb = W1[(64 + kb) * H1 + n] - W1[(128 + kb) * H1 + n] + qsh[kb] * W1[(192 + kb) * H1 + n];
            *(float2*)&wfr[2 * fp] = make_float2(va, vb);
        }
        if (tid < 320) {
            int h = tid % 80, chunk = tid / 80;
            float acc = (chunk == 0) ? b1[h] : 0.0f;
            int e0 = chunk * 16;
            #pragma unroll 16
            for (int e = e0; e < e0 + 16; e++)
                acc += qsh[e] * (W1[e * H1 + h] + W1[(128 + e) * H1 + h]);
            c1p[chunk * 80 + h] = acc;
        }

        asm volatile("cp.async.wait_group 1;");   // facts(bi) landed
        __syncthreads();
        if (tid < H1) c1sh[tid] = c1p[tid] + c1p[80 + tid] + c1p[160 + tid] + c1p[240 + tid];
        __syncthreads();

        const uint32_t* fu = (const uint32_t*)(parity ? fsh1 : fsh0);
        const float*    fsh = parity ? fsh1 : fsh0;

        // ---- D: MLP, one 16-row stripe per warp (warps 0..12) ----
        if (w < NSTRIPES) {
            const int r0 = w * 16;

            float acc[10][4];
            #pragma unroll
            for (int j = 0; j < 10; j++)
                #pragma unroll
                for (int q = 0; q < 4; q++) acc[j][q] = 0.0f;

            #pragma unroll
            for (int kt = 0; kt < 8; kt++) {
                const int k0 = kt * 8 + tg;
                uint32_t a[4];
                a[0] = fu[(r0 + g    ) * FS + k0    ];
                a[1] = fu[(r0 + g + 8) * FS + k0    ];
                a[2] = fu[(r0 + g    ) * FS + k0 + 4];
                a[3] = fu[(r0 + g + 8) * FS + k0 + 4];
                const float2* wp = (const float2*)wfr + kt * 320 + lane;
                #pragma unroll
                for (int j = 0; j < 10; j++) {
                    float2 bw = wp[j * 32];
                    uint32_t bf[2] = { __float_as_uint(bw.x), __float_as_uint(bw.y) };
                    mma_tf32(acc[j], a, bf);
                }
            }

            // sigmoid + direct fragment renaming + GEMM2 (no shfl)
            float acc2[5][4];
            #pragma unroll
            for (int j = 0; j < 5; j++)
                #pragma unroll
                for (int q = 0; q < 4; q++) acc2[j][q] = 0.0f;

            #pragma unroll
            for (int kt = 0; kt < 10; kt++) {
                const float c1a = c1sh[kt * 8 + tg];
                const float c1b = c1sh[kt * 8 + tg + 4];
                float h0  = sigm(acc[kt][0] + c1a);
                float h1v = sigm(acc[kt][1] + c1b);
                float h2v = sigm(acc[kt][2] + c1a);
                float h3  = sigm(acc[kt][3] + c1b);

                uint32_t a[4] = { __float_as_uint(h0), __float_as_uint(h2v),
                                  __float_as_uint(h1v), __float_as_uint(h3) };
                const float2* wp2 = (const float2*)w2fr + kt * 160 + lane;
                #pragma unroll
                for (int j = 0; j < 5; j++) {
                    float2 bw = wp2[j * 32];
                    uint32_t bf[2] = { __float_as_uint(bw.x), __float_as_uint(bw.y) };
                    mma_tf32(acc2[j], a, bf);
                }
            }

            // epilogue: sigmoid, dot W3, quad-reduce, scores -> smem
            float s_lo = 0.0f, s_hi = 0.0f;
            #pragma unroll
            for (int j = 0; j < 5; j++) {
                const int n0 = j * 8 + 2 * tg;
                float bb0 = b2sh[n0], bb1 = b2sh[n0 + 1];
                float w30 = w3sh[n0], w31 = w3sh[n0 + 1];
                s_lo += sigm(acc2[j][0] + bb0) * w30 + sigm(acc2[j][1] + bb1) * w31;
                s_hi += sigm(acc2[j][2] + bb0) * w30 + sigm(acc2[j][3] + bb1) * w31;
            }
            s_lo += __shfl_xor_sync(0xFFFFFFFF, s_lo, 1);
            s_lo += __shfl_xor_sync(0xFFFFFFFF, s_lo, 2);
            s_hi += __shfl_xor_sync(0xFFFFFFFF, s_hi, 1);
            s_hi += __shfl_xor_sync(0xFFFFFFFF, s_hi, 2);
            if (tg == 0) {   // b3 omitted: constant shift cancels in softmax
                scoresh[r0 + g]     = s_lo;
                scoresh[r0 + g + 8] = s_hi;
            }
        }
        __syncthreads();

        // ---- E: masked softmax over T ----
        const float PADV = -4294967295.0f;   // -2^32 + 1
        float v = (tid < T_LEN) ? ((mbit == 1) ? scoresh[tid] : PADV) : -INFINITY;

        float m = v;
        #pragma unroll
        for (int off = 16; off > 0; off >>= 1)
            m = fmaxf(m, __shfl_xor_sync(0xFFFFFFFF, m, off));
        if (lane == 0) red[w] = m;
        __syncthreads();
        float mmax = red[0];
        #pragma unroll
        for (int i = 1; i < 16; i++) mmax = fmaxf(mmax, red[i]);

        float p = (tid < T_LEN) ? __expf(v - mmax) : 0.0f;
        float ssum = p;
        #pragma unroll
        for (int off = 16; off > 0; off >>= 1)
            ssum += __shfl_xor_sync(0xFFFFFFFF, ssum, off);
        if (lane == 0) red[16 + w] = ssum;
        __syncthreads();
        float tot = red[16];
        #pragma unroll
        for (int i = 17; i < 32; i++) tot += red[i];
        float inv = 1.0f / tot;
        if (tid < ROWS) attnsh[tid] = p * inv;   // rows >= T_LEN get 0
        __syncthreads();

        // ---- F: out[bi] = attn @ facts (smem-resident) ----
        {
            const int e = tid & 63;
            const int c = tid >> 6;              // 8 chunks of 26 rows
            float acc = 0.0f;
            const int t0 = c * 26;
            #pragma unroll 13
            for (int t = t0; t < t0 + 26; t++)
                acc = fmaf(attnsh[t], fsh[t * FS + e], acc);
            outred[c * 64 + e] = acc;
        }
        __syncthreads();    // also orders this batch's fsh reads before next prefetch
        if (tid < E_DIM) {
            float o = 0.0f;
            #pragma unroll
            for (int c = 0; c < 8; c++) o += outred[c * 64 + tid];
            out[(size_t)bi * E_DIM + tid] = o;
        }
    }
}

// ============================================================================
// launch
// ============================================================================
static inline size_t persistent_smem_bytes() {
    size_t f = 2 * (size_t)FSH_ELEMS + 5120 + 3200 + H1 + 320 + H2 + H2 +
               ROWS + 32 + ROWS + NTHREADS + E_DIM;
    return f * sizeof(float);
}

extern "C" void kernel_launch(void* const* d_in, const int* in_sizes, int n_in,
                              void* d_out, int out_size)
{
    const float* query = (const float*)d_in[0];
    const float* facts = (const float*)d_in[1];
    const int*   mask  = (const int*)  d_in[2];
    const float* W1    = (const float*)d_in[3];
    const float* b1    = (const float*)d_in[4];
    const float* W2    = (const float*)d_in[5];
    const float* b2    = (const float*)d_in[6];
    const float* W3    = (const float*)d_in[7];
    float* out = (float*)d_out;

    const int B = in_sizes[0] / E_DIM;

    static int nsm = 0;
    if (nsm == 0) {
        cudaDeviceGetAttribute(&nsm, cudaDevAttrMultiProcessorCount, 0);
        if (nsm <= 0) nsm = 148;
        cudaFuncSetAttribute(persistent_kernel,
                             cudaFuncAttributeMaxDynamicSharedMemorySize,
                             (int)persistent_smem_bytes());
    }

    int grid = (B < nsm) ? B : nsm;
    persistent_kernel<<<grid, NTHREADS, persistent_smem_bytes()>>>(
        query, facts, mask, W1, b1, W2, b2, W3, out, B);
}

// round 13
// speedup vs baseline: 1.2340x; 1.2340x over previous
#include <cuda_runtime.h>
#include <cuda_fp16.h>
#include <math.h>
#include <stdint.h>

#define T_LEN 200
#define E_DIM 64
#define H1 80
#define H2 40
#define NTHREADS 256
#define NSTRIPES 13        // 208 rows = 13 * 16
#define ROWS (16 * NSTRIPES)

#define FH 36              // facts f16 tile stride in u32(half2) units = 72 halves

__device__ __forceinline__ float sigm(float x) {
    float t;
    asm("tanh.approx.f32 %0, %1;" : "=f"(t) : "f"(0.5f * x));
    return fmaf(0.5f, t, 0.5f);
}
__device__ __forceinline__ uint32_t pack_h2(float lo, float hi) {
    uint32_t r;
    asm("cvt.rn.f16x2.f32 %0, %1, %2;" : "=r"(r) : "f"(hi), "f"(lo));  // %1 -> high half
    return r;
}
__device__ __forceinline__ void mma_f16(float c[4], const uint32_t a[4], uint32_t b0, uint32_t b1) {
    asm volatile(
        "mma.sync.aligned.m16n8k16.row.col.f32.f16.f16.f32 "
        "{%0,%1,%2,%3}, {%4,%5,%6,%7}, {%8,%9}, {%0,%1,%2,%3};"
        : "+f"(c[0]), "+f"(c[1]), "+f"(c[2]), "+f"(c[3])
        : "r"(a[0]), "r"(a[1]), "r"(a[2]), "r"(a[3]), "r"(b0), "r"(b1));
}

// ============================================================================
// Fused kernel, fp16 tensor-core MLP. One CTA per batch, 3 CTAs/SM.
// ============================================================================
__global__ __launch_bounds__(NTHREADS, 3)
void fused_kernel(const float* __restrict__ query,
                  const float* __restrict__ facts,
                  const int*   __restrict__ mask,
                  const float* __restrict__ W1,
                  const float* __restrict__ b1,
                  const float* __restrict__ W2,
                  const float* __restrict__ b2,
                  const float* __restrict__ W3,
                  float* __restrict__ out)
{
    extern __shared__ float sm[];
    uint32_t* fshh = (uint32_t*)sm;            // [208][36] half2 facts tile
    uint32_t* wfr  = fshh + ROWS * FH;         // [1280] uint2 = 2560 u32 (wefft f16 frags)
    uint32_t* w2fr = wfr + 2560;               // [800] uint2 = 1600 u32 (W2 f16 frags)
    float* c1sh    = (float*)(w2fr + 1600);    // [80]
    float* b2sh    = c1sh + H1;                // [40]
    float* w3sh    = b2sh + H2;                // [40]
    float* scoresh = w3sh + H2;                // [208]
    float* red     = scoresh + ROWS;           // [16]
    float* attnsh  = red + 16;                 // [208]
    float* outred  = attnsh + ROWS;            // [512]
    float* qsh     = outred + 512;             // [64]

    const int b    = blockIdx.x;
    const int tid  = threadIdx.x;
    const int w    = tid >> 5;
    const int lane = tid & 31;
    const int g    = lane >> 2;
    const int tg   = lane & 3;

    // ---------------- staging: facts -> f16 tile ----------------
    {
        const float4* fb = (const float4*)(facts + (size_t)b * T_LEN * E_DIM);
        for (int i = tid; i < T_LEN * 16; i += NTHREADS) {
            int t = i >> 4, e4 = i & 15;
            float4 v = fb[i];
            uint2 h;
            h.x = pack_h2(v.x, v.y);
            h.y = pack_h2(v.z, v.w);
            *(uint2*)&fshh[t * FH + e4 * 2] = h;
        }
        // zero pad rows [200,208): 8 rows * 18 uint2
        for (int i = tid; i < 144; i += NTHREADS) {
            int t = T_LEN + i / 18, c = i % 18;
            *(uint2*)&fshh[t * FH + c * 2] = make_uint2(0u, 0u);
        }
    }
    int mbit = (tid < T_LEN) ? mask[(size_t)b * T_LEN + tid] : 0;
    if (tid < E_DIM) qsh[tid] = query[(size_t)b * E_DIM + tid];
    if (tid < H2)    { b2sh[tid] = b2[tid]; w3sh[tid] = W3[tid]; }
    __syncthreads();    // qsh ready

    // ---------------- per-batch effective layer-1 weights (f16 fragments) ------
    // wefft[n][k] = W1[(64+k)*80+n] - W1[(128+k)*80+n] + q[k]*W1[(192+k)*80+n]
    // fragment fp = kt*320 + j*32 + lane -> b0 = (k0,k0+1), b1 = (k0+8,k0+9), n=j*8+g
    for (int fp = tid; fp < 1280; fp += NTHREADS) {
        int kt = fp / 320, rem = fp - kt * 320;
        int j = rem >> 5, l5 = rem & 31;
        int gg = l5 >> 2, tt = l5 & 3;
        int n = j * 8 + gg;
        int k0 = kt * 16 + tt * 2;
        float v0 = W1[(64 + k0    ) * H1 + n] - W1[(128 + k0    ) * H1 + n] + qsh[k0    ] * W1[(192 + k0    ) * H1 + n];
        float v1 = W1[(64 + k0 + 1) * H1 + n] - W1[(128 + k0 + 1) * H1 + n] + qsh[k0 + 1] * W1[(192 + k0 + 1) * H1 + n];
        float v8 = W1[(64 + k0 + 8) * H1 + n] - W1[(128 + k0 + 8) * H1 + n] + qsh[k0 + 8] * W1[(192 + k0 + 8) * H1 + n];
        float v9 = W1[(64 + k0 + 9) * H1 + n] - W1[(128 + k0 + 9) * H1 + n] + qsh[k0 + 9] * W1[(192 + k0 + 9) * H1 + n];
        uint2 h;
        h.x = pack_h2(v0, v1);
        h.y = pack_h2(v8, v9);
        *(uint2*)&wfr[fp * 2] = h;
    }
    // W2 fragments: fp = kt2*160 + j2*32 + lane
    for (int fp = tid; fp < 800; fp += NTHREADS) {
        int kt = fp / 160, rem = fp - kt * 160;
        int j2 = rem >> 5, l5 = rem & 31;
        int gg = l5 >> 2, tt = l5 & 3;
        int n = j2 * 8 + gg;
        int k0 = kt * 16 + tt * 2;
        uint2 h;
        h.x = pack_h2(W2[k0 * H2 + n],       W2[(k0 + 1) * H2 + n]);
        h.y = pack_h2(W2[(k0 + 8) * H2 + n], W2[(k0 + 9) * H2 + n]);
        *(uint2*)&w2fr[fp * 2] = h;
    }
    // c1 = b1 + q@(A+C)
    if (tid < H1) {
        float acc = b1[tid];
        #pragma unroll 8
        for (int e = 0; e < E_DIM; e++)
            acc += qsh[e] * (W1[e * H1 + tid] + W1[(128 + e) * H1 + tid]);
        c1sh[tid] = acc;
    }
    __syncthreads();

    // ---------------- per-stripe MLP (warp w handles stripes w, w+8) ------------
    for (int s = w; s < NSTRIPES; s += 8) {
        const int r0 = s * 16;

        // GEMM1: acc = F @ Weff^T  (4 k16-tiles)
        float acc[10][4];
        #pragma unroll
        for (int j = 0; j < 10; j++)
            #pragma unroll
            for (int q = 0; q < 4; q++) acc[j][q] = 0.0f;

        #pragma unroll
        for (int kt = 0; kt < 4; kt++) {
            const int base = (r0 + g) * FH + kt * 8 + tg;
            uint32_t a[4];
            a[0] = fshh[base];                 // row g,   k lo
            a[1] = fshh[base + 8 * FH];        // row g+8, k lo
            a[2] = fshh[base + 4];             // row g,   k hi
            a[3] = fshh[base + 8 * FH + 4];    // row g+8, k hi
            const uint2* wp = (const uint2*)wfr + kt * 320 + lane;
            #pragma unroll
            for (int j = 0; j < 10; j++) {
                uint2 bw = wp[j * 32];
                mma_f16(acc[j], a, bw.x, bw.y);
            }
        }

        // sigmoid + f16x2 pack (C-frag pairs == A-frag pairs) + GEMM2 (5 k16-tiles)
        float acc2[5][4];
        #pragma unroll
        for (int j = 0; j < 5; j++)
            #pragma unroll
            for (int q = 0; q < 4; q++) acc2[j][q] = 0.0f;

        #pragma unroll
        for (int kt2 = 0; kt2 < 5; kt2++) {
            const int ja = 2 * kt2, jb = ja + 1;
            const float ca0 = c1sh[8 * ja + 2 * tg], ca1 = c1sh[8 * ja + 2 * tg + 1];
            const float cb0 = c1sh[8 * jb + 2 * tg], cb1 = c1sh[8 * jb + 2 * tg + 1];
            uint32_t a[4];
            a[0] = pack_h2(sigm(acc[ja][0] + ca0), sigm(acc[ja][1] + ca1));  // row g,   k lo
            a[1] = pack_h2(sigm(acc[ja][2] + ca0), sigm(acc[ja][3] + ca1));  // row g+8, k lo
            a[2] = pack_h2(sigm(acc[jb][0] + cb0), sigm(acc[jb][1] + cb1));  // row g,   k hi
            a[3] = pack_h2(sigm(acc[jb][2] + cb0), sigm(acc[jb][3] + cb1));  // row g+8, k hi
            const uint2* wp2 = (const uint2*)w2fr + kt2 * 160 + lane;
            #pragma unroll
            for (int j2 = 0; j2 < 5; j2++) {
                uint2 bw = wp2[j2 * 32];
                mma_f16(acc2[j2], a, bw.x, bw.y);
            }
        }

        // epilogue: sigmoid, dot W3, quad-reduce, scores -> smem
        float s_lo = 0.0f, s_hi = 0.0f;
        #pragma unroll
        for (int j = 0; j < 5; j++) {
            const int n0 = j * 8 + 2 * tg;
            float bb0 = b2sh[n0], bb1 = b2sh[n0 + 1];
            float w30 = w3sh[n0], w31 = w3sh[n0 + 1];
            s_lo += sigm(acc2[j][0] + bb0) * w30 + sigm(acc2[j][1] + bb1) * w31;
            s_hi += sigm(acc2[j][2] + bb0) * w30 + sigm(acc2[j][3] + bb1) * w31;
        }
        s_lo += __shfl_xor_sync(0xFFFFFFFF, s_lo, 1);
        s_lo += __shfl_xor_sync(0xFFFFFFFF, s_lo, 2);
        s_hi += __shfl_xor_sync(0xFFFFFFFF, s_hi, 1);
        s_hi += __shfl_xor_sync(0xFFFFFFFF, s_hi, 2);

        if (tg == 0) {   // b3 omitted: constant shift cancels in softmax
            scoresh[r0 + g]     = s_lo;
            scoresh[r0 + g + 8] = s_hi;
        }
    }
    __syncthreads();

    // ---------------- masked softmax over T (warp-shuffle reductions) ----------
    const float PADV = -4294967295.0f;   // -2^32 + 1
    float v = (tid < T_LEN) ? ((mbit == 1) ? scoresh[tid] : PADV) : -INFINITY;

    float m = v;
    #pragma unroll
    for (int off = 16; off > 0; off >>= 1)
        m = fmaxf(m, __shfl_xor_sync(0xFFFFFFFF, m, off));
    if (lane == 0) red[w] = m;
    __syncthreads();
    float mmax = red[0];
    #pragma unroll
    for (int i = 1; i < 8; i++) mmax = fmaxf(mmax, red[i]);

    float p = (tid < T_LEN) ? __expf(v - mmax) : 0.0f;
    float ssum = p;
    #pragma unroll
    for (int off = 16; off > 0; off >>= 1)
        ssum += __shfl_xor_sync(0xFFFFFFFF, ssum, off);
    if (lane == 0) red[8 + w] = ssum;
    __syncthreads();
    float tot = red[8];
    #pragma unroll
    for (int i = 9; i < 16; i++) tot += red[i];
    float inv = 1.0f / tot;
    if (tid < ROWS) attnsh[tid] = p * inv;    // rows >= T_LEN get 0
    __syncthreads();

    // ---------------- out[b] = attn @ facts (f16 tile, fp32 accumulate) --------
    {
        const int e2 = tid & 31;       // half2 column
        const int c  = tid >> 5;       // 8 chunks of 26 rows
        float ax = 0.0f, ay = 0.0f;
        const int t0 = c * 26;
        #pragma unroll 13
        for (int t = t0; t < t0 + 26; t++) {
            uint32_t h = fshh[t * FH + e2];
            float2 f = __half22float2(*(__half2*)&h);
            float at = attnsh[t];
            ax = fmaf(at, f.x, ax);
            ay = fmaf(at, f.y, ay);
        }
        outred[c * 64 + 2 * e2]     = ax;
        outred[c * 64 + 2 * e2 + 1] = ay;
    }
    __syncthreads();
    if (tid < E_DIM) {
        float o = 0.0f;
        #pragma unroll
        for (int c = 0; c < 8; c++) o += outred[c * 64 + tid];
        out[(size_t)b * E_DIM + tid] = o;
    }
}

// ============================================================================
// launch
// ============================================================================
static inline size_t fused_smem_bytes() {
    size_t u32s = (size_t)ROWS * FH + 2560 + 1600;                 // f16/frag areas
    size_t flts = H1 + H2 + H2 + ROWS + 16 + ROWS + 512 + E_DIM;   // fp32 areas
    return (u32s + flts) * 4;
}

extern "C" void kernel_launch(void* const* d_in, const int* in_sizes, int n_in,
                              void* d_out, int out_size)
{
    const float* query = (const float*)d_in[0];
    const float* facts = (const float*)d_in[1];
    const int*   mask  = (const int*)  d_in[2];
    const float* W1    = (const float*)d_in[3];
    const float* b1    = (const float*)d_in[4];
    const float* W2    = (const float*)d_in[5];
    const float* b2    = (const float*)d_in[6];
    const float* W3    = (const float*)d_in[7];
    float* out = (float*)d_out;

    const int B = in_sizes[0] / E_DIM;

    static bool configured = false;
    if (!configured) {
        cudaFuncSetAttribute(fused_kernel,
                             cudaFuncAttributeMaxDynamicSharedMemorySize,
                             (int)fused_smem_bytes());
        configured = true;
    }

    fused_kernel<<<B, NTHREADS, fused_smem_bytes()>>>(query, facts, mask,
                                                      W1, b1, W2, b2, W3, out);
}

// round 14
// speedup vs baseline: 1.3738x; 1.1132x over previous
#include <cuda_runtime.h>
#include <cuda_fp16.h>
#include <math.h>
#include <stdint.h>

#define T_LEN 200
#define E_DIM 64
#define H1 80
#define H2 40
#define NTHREADS 256
#define NSTRIPES 13        // 208 rows = 13 * 16
#define ROWS (16 * NSTRIPES)

#define FH 36              // facts f16 tile stride in u32(half2) units = 72 halves

// batch-invariant precomputed arrays (prep_kernel fills once per launch)
static __device__ float4 g_bc4[1280];    // (B-C) in fragment order: (k0,k0+1,k0+8,k0+9)
static __device__ float4 g_d4[1280];     // D     in fragment order
static __device__ uint2  g_w2f[800];     // W2 fragments, f16-packed
static __device__ float  g_ac[E_DIM * H1];  // A+C (for c1 GEMV)

__device__ __forceinline__ float sigm(float x) {
    float t;
    asm("tanh.approx.f32 %0, %1;" : "=f"(t) : "f"(0.5f * x));
    return fmaf(0.5f, t, 0.5f);
}
__device__ __forceinline__ uint32_t pack_h2(float lo, float hi) {
    uint32_t r;
    asm("cvt.rn.f16x2.f32 %0, %1, %2;" : "=r"(r) : "f"(hi), "f"(lo));  // %1 -> high half
    return r;
}
__device__ __forceinline__ void mma_f16(float c[4], const uint32_t a[4], uint32_t b0, uint32_t b1) {
    asm volatile(
        "mma.sync.aligned.m16n8k16.row.col.f32.f16.f16.f32 "
        "{%0,%1,%2,%3}, {%4,%5,%6,%7}, {%8,%9}, {%0,%1,%2,%3};"
        : "+f"(c[0]), "+f"(c[1]), "+f"(c[2]), "+f"(c[3])
        : "r"(a[0]), "r"(a[1]), "r"(a[2]), "r"(a[3]), "r"(b0), "r"(b1));
}

// ============================================================================
// Prep: batch-invariant fragment packing (runs once per launch; ~60 KB writes)
// ============================================================================
__global__ __launch_bounds__(NTHREADS)
void prep_kernel(const float* __restrict__ W1, const float* __restrict__ W2)
{
    const int idx = blockIdx.x * NTHREADS + threadIdx.x;
    const int nth = gridDim.x * NTHREADS;

    // (B-C) and D fragments: fp -> k0 = (fp/320)*16 + (fp&3)*2, n = j*8+gg
    for (int fp = idx; fp < 1280; fp += nth) {
        int kt = fp / 320, rem = fp - kt * 320;
        int j = rem >> 5, l5 = rem & 31;
        int gg = l5 >> 2, tt = l5 & 3;
        int n = j * 8 + gg;
        int k0 = kt * 16 + tt * 2;
        float4 bc, d;
        bc.x = W1[(64 + k0    ) * H1 + n] - W1[(128 + k0    ) * H1 + n];
        bc.y = W1[(64 + k0 + 1) * H1 + n] - W1[(128 + k0 + 1) * H1 + n];
        bc.z = W1[(64 + k0 + 8) * H1 + n] - W1[(128 + k0 + 8) * H1 + n];
        bc.w = W1[(64 + k0 + 9) * H1 + n] - W1[(128 + k0 + 9) * H1 + n];
        d.x  = W1[(192 + k0    ) * H1 + n];
        d.y  = W1[(192 + k0 + 1) * H1 + n];
        d.z  = W1[(192 + k0 + 8) * H1 + n];
        d.w  = W1[(192 + k0 + 9) * H1 + n];
        g_bc4[fp] = bc;
        g_d4[fp]  = d;
    }
    // W2 fragments, f16-packed
    for (int fp = idx; fp < 800; fp += nth) {
        int kt = fp / 160, rem = fp - kt * 160;
        int j2 = rem >> 5, l5 = rem & 31;
        int gg = l5 >> 2, tt = l5 & 3;
        int n = j2 * 8 + gg;
        int k0 = kt * 16 + tt * 2;
        uint2 h;
        h.x = pack_h2(W2[k0 * H2 + n],       W2[(k0 + 1) * H2 + n]);
        h.y = pack_h2(W2[(k0 + 8) * H2 + n], W2[(k0 + 9) * H2 + n]);
        g_w2f[fp] = h;
    }
    // A+C for the c1 GEMV
    for (int i = idx; i < E_DIM * H1; i += nth)
        g_ac[i] = W1[i] + W1[128 * H1 + i];
}

// ============================================================================
// Fused kernel, fp16 tensor-core MLP. One CTA per batch, 3 CTAs/SM.
// ============================================================================
__global__ __launch_bounds__(NTHREADS, 3)
void fused_kernel(const float* __restrict__ query,
                  const float* __restrict__ facts,
                  const int*   __restrict__ mask,
                  const float* __restrict__ b1,
                  const float* __restrict__ b2,
                  const float* __restrict__ W3,
                  float* __restrict__ out)
{
    extern __shared__ float sm[];
    uint32_t* fshh = (uint32_t*)sm;            // [208][36] half2 facts tile
    uint32_t* wfr  = fshh + ROWS * FH;         // [1280] uint2 = 2560 u32 (wefft f16 frags)
    uint32_t* w2fr = wfr + 2560;               // [800] uint2 = 1600 u32 (W2 f16 frags)
    float* c1sh    = (float*)(w2fr + 1600);    // [80]
    float* b2sh    = c1sh + H1;                // [40]
    float* w3sh    = b2sh + H2;                // [40]
    float* scoresh = w3sh + H2;                // [208]
    float* red     = scoresh + ROWS;           // [16]
    float* attnsh  = red + 16;                 // [208]
    float* outred  = attnsh + ROWS;            // [512]
    float* qsh     = outred + 512;             // [64]

    const int b    = blockIdx.x;
    const int tid  = threadIdx.x;
    const int w    = tid >> 5;
    const int lane = tid & 31;
    const int g    = lane >> 2;
    const int tg   = lane & 3;

    // ---------------- staging: facts -> f16 tile ----------------
    {
        const float4* fb = (const float4*)(facts + (size_t)b * T_LEN * E_DIM);
        for (int i = tid; i < T_LEN * 16; i += NTHREADS) {
            int t = i >> 4, e4 = i & 15;
            float4 v = fb[i];
            uint2 h;
            h.x = pack_h2(v.x, v.y);
            h.y = pack_h2(v.z, v.w);
            *(uint2*)&fshh[t * FH + e4 * 2] = h;
        }
        // zero pad rows [200,208): 8 rows * 18 uint2
        for (int i = tid; i < 144; i += NTHREADS) {
            int t = T_LEN + i / 18, c = i % 18;
            *(uint2*)&fshh[t * FH + c * 2] = make_uint2(0u, 0u);
        }
    }
    int mbit = (tid < T_LEN) ? mask[(size_t)b * T_LEN + tid] : 0;
    if (tid < E_DIM) qsh[tid] = query[(size_t)b * E_DIM + tid];
    if (tid < H2)    { b2sh[tid] = b2[tid]; w3sh[tid] = W3[tid]; }
    // W2 fragment copy: pure vector loads
    {
        const uint4* src = (const uint4*)g_w2f;
        uint4* dst = (uint4*)w2fr;
        for (int i = tid; i < 400; i += NTHREADS) dst[i] = src[i];
    }
    __syncthreads();    // qsh ready

    // ---------------- per-batch wefft fragments from precomputed BC/D ----------
    // wefft pair values: v = bc + q[k]*d, fragment order matches g_bc4/g_d4.
    for (int fp = tid; fp < 1280; fp += NTHREADS) {
        int k0 = (fp / 320) * 16 + (fp & 3) * 2;
        float4 bc = g_bc4[fp];
        float4 d  = g_d4[fp];
        float q0 = qsh[k0], q1 = qsh[k0 + 1], q8 = qsh[k0 + 8], q9 = qsh[k0 + 9];
        uint2 h;
        h.x = pack_h2(fmaf(q0, d.x, bc.x), fmaf(q1, d.y, bc.y));
        h.y = pack_h2(fmaf(q8, d.z, bc.z), fmaf(q9, d.w, bc.w));
        *(uint2*)&wfr[fp * 2] = h;
    }
    // c1 = b1 + q@(A+C)  (A+C precomputed)
    if (tid < H1) {
        float acc = b1[tid];
        #pragma unroll 8
        for (int e = 0; e < E_DIM; e++)
            acc += qsh[e] * g_ac[e * H1 + tid];
        c1sh[tid] = acc;
    }
    __syncthreads();

    // ---------------- per-stripe MLP (warp w handles stripes w, w+8) ------------
    for (int s = w; s < NSTRIPES; s += 8) {
        const int r0 = s * 16;

        // GEMM1: acc = F @ Weff^T  (4 k16-tiles)
        float acc[10][4];
        #pragma unroll
        for (int j = 0; j < 10; j++)
            #pragma unroll
            for (int q = 0; q < 4; q++) acc[j][q] = 0.0f;

        #pragma unroll
        for (int kt = 0; kt < 4; kt++) {
            const int base = (r0 + g) * FH + kt * 8 + tg;
            uint32_t a[4];
            a[0] = fshh[base];                 // row g,   k lo
            a[1] = fshh[base + 8 * FH];        // row g+8, k lo
            a[2] = fshh[base + 4];             // row g,   k hi
            a[3] = fshh[base + 8 * FH + 4];    // row g+8, k hi
            const uint2* wp = (const uint2*)wfr + kt * 320 + lane;
            #pragma unroll
            for (int j = 0; j < 10; j++) {
                uint2 bw = wp[j * 32];
                mma_f16(acc[j], a, bw.x, bw.y);
            }
        }

        // sigmoid + f16x2 pack (C-frag pairs == A-frag pairs) + GEMM2 (5 k16-tiles)
        float acc2[5][4];
        #pragma unroll
        for (int j = 0; j < 5; j++)
            #pragma unroll
            for (int q = 0; q < 4; q++) acc2[j][q] = 0.0f;

        #pragma unroll
        for (int kt2 = 0; kt2 < 5; kt2++) {
            const int ja = 2 * kt2, jb = ja + 1;
            const float ca0 = c1sh[8 * ja + 2 * tg], ca1 = c1sh[8 * ja + 2 * tg + 1];
            const float cb0 = c1sh[8 * jb + 2 * tg], cb1 = c1sh[8 * jb + 2 * tg + 1];
            uint32_t a[4];
            a[0] = pack_h2(sigm(acc[ja][0] + ca0), sigm(acc[ja][1] + ca1));  // row g,   k lo
            a[1] = pack_h2(sigm(acc[ja][2] + ca0), sigm(acc[ja][3] + ca1));  // row g+8, k lo
            a[2] = pack_h2(sigm(acc[jb][0] + cb0), sigm(acc[jb][1] + cb1));  // row g,   k hi
            a[3] = pack_h2(sigm(acc[jb][2] + cb0), sigm(acc[jb][3] + cb1));  // row g+8, k hi
            const uint2* wp2 = (const uint2*)w2fr + kt2 * 160 + lane;
            #pragma unroll
            for (int j2 = 0; j2 < 5; j2++) {
                uint2 bw = wp2[j2 * 32];
                mma_f16(acc2[j2], a, bw.x, bw.y);
            }
        }

        // epilogue: sigmoid, dot W3, quad-reduce, scores -> smem
        float s_lo = 0.0f, s_hi = 0.0f;
        #pragma unroll
        for (int j = 0; j < 5; j++) {
            const int n0 = j * 8 + 2 * tg;
            float bb0 = b2sh[n0], bb1 = b2sh[n0 + 1];
            float w30 = w3sh[n0], w31 = w3sh[n0 + 1];
            s_lo += sigm(acc2[j][0] + bb0) * w30 + sigm(acc2[j][1] + bb1) * w31;
            s_hi += sigm(acc2[j][2] + bb0) * w30 + sigm(acc2[j][3] + bb1) * w31;
        }
        s_lo += __shfl_xor_sync(0xFFFFFFFF, s_lo, 1);
        s_lo += __shfl_xor_sync(0xFFFFFFFF, s_lo, 2);
        s_hi += __shfl_xor_sync(0xFFFFFFFF, s_hi, 1);
        s_hi += __shfl_xor_sync(0xFFFFFFFF, s_hi, 2);

        if (tg == 0) {   // b3 omitted: constant shift cancels in softmax
            scoresh[r0 + g]     = s_lo;
            scoresh[r0 + g + 8] = s_hi;
        }
    }
    __syncthreads();

    // ---------------- masked softmax over T (warp-shuffle reductions) ----------
    const float PADV = -4294967295.0f;   // -2^32 + 1
    float v = (tid < T_LEN) ? ((mbit == 1) ? scoresh[tid] : PADV) : -INFINITY;

    float m = v;
    #pragma unroll
    for (int off = 16; off > 0; off >>= 1)
        m = fmaxf(m, __shfl_xor_sync(0xFFFFFFFF, m, off));
    if (lane == 0) red[w] = m;
    __syncthreads();
    float mmax = red[0];
    #pragma unroll
    for (int i = 1; i < 8; i++) mmax = fmaxf(mmax, red[i]);

    float p = (tid < T_LEN) ? __expf(v - mmax) : 0.0f;
    float ssum = p;
    #pragma unroll
    for (int off = 16; off > 0; off >>= 1)
        ssum += __shfl_xor_sync(0xFFFFFFFF, ssum, off);
    if (lane == 0) red[8 + w] = ssum;
    __syncthreads();
    float tot = red[8];
    #pragma unroll
    for (int i = 9; i < 16; i++) tot += red[i];
    float inv = 1.0f / tot;
    if (tid < ROWS) attnsh[tid] = p * inv;    // rows >= T_LEN get 0
    __syncthreads();

    // ---------------- out[b] = attn @ facts (f16 tile, fp32 accumulate) --------
    {
        const int e2 = tid & 31;       // half2 column
        const int c  = tid >> 5;       // 8 chunks of 26 rows
        float ax = 0.0f, ay = 0.0f;
        const int t0 = c * 26;
        #pragma unroll 13
        for (int t = t0; t < t0 + 26; t++) {
            uint32_t h = fshh[t * FH + e2];
            float2 f = __half22float2(*(__half2*)&h);
            float at = attnsh[t];
            ax = fmaf(at, f.x, ax);
            ay = fmaf(at, f.y, ay);
        }
        outred[c * 64 + 2 * e2]     = ax;
        outred[c * 64 + 2 * e2 + 1] = ay;
    }
    __syncthreads();
    if (tid < E_DIM) {
        float o = 0.0f;
        #pragma unroll
        for (int c = 0; c < 8; c++) o += outred[c * 64 + tid];
        out[(size_t)b * E_DIM + tid] = o;
    }
}

// ============================================================================
// launch
// ============================================================================
static inline size_t fused_smem_bytes() {
    size_t u32s = (size_t)ROWS * FH + 2560 + 1600;                 // f16/frag areas
    size_t flts = H1 + H2 + H2 + ROWS + 16 + ROWS + 512 + E_DIM;   // fp32 areas
    return (u32s + flts) * 4;
}

extern "C" void kernel_launch(void* const* d_in, const int* in_sizes, int n_in,
                              void* d_out, int out_size)
{
    const float* query = (const float*)d_in[0];
    const float* facts = (const float*)d_in[1];
    const int*   mask  = (const int*)  d_in[2];
    const float* W1    = (const float*)d_in[3];
    const float* b1    = (const float*)d_in[4];
    const float* W2    = (const float*)d_in[5];
    const float* b2    = (const float*)d_in[6];
    const float* W3    = (const float*)d_in[7];
    float* out = (float*)d_out;

    const int B = in_sizes[0] / E_DIM;

    static bool configured = false;
    if (!configured) {
        cudaFuncSetAttribute(fused_kernel,
                             cudaFuncAttributeMaxDynamicSharedMemorySize,
                             (int)fused_smem_bytes());
        configured = true;
    }

    prep_kernel<<<16, NTHREADS>>>(W1, W2);
    fused_kernel<<<B, NTHREADS, fused_smem_bytes()>>>(query, facts, mask,
                                                      b1, b2, W3, out);
}

// round 15
// speedup vs baseline: 1.5282x; 1.1124x over previous
#include <cuda_runtime.h>
#include <cuda_fp16.h>
#include <math.h>
#include <stdint.h>

#define T_LEN 200
#define E_DIM 64
#define H1 80
#define H2 40
#define NTHREADS 256
#define NSTRIPES 13        // 208 rows = 13 * 16
#define ROWS (16 * NSTRIPES)

#define FH 36              // facts f16 tile stride in u32(half2) units = 72 halves

// batch-invariant precomputed arrays (prep_kernel fills once per launch)
static __device__ float4 g_bc4[1280];    // (B-C) in fragment order: (k0,k0+1,k0+8,k0+9)
static __device__ float4 g_d4[1280];     // D     in fragment order
static __device__ uint2  g_w2f[800];     // W2 fragments, f16-packed
static __device__ float  g_ac[E_DIM * H1];  // A+C (for c1 GEMV)

__device__ __forceinline__ float sigm(float x) {
    float t;
    asm("tanh.approx.f32 %0, %1;" : "=f"(t) : "f"(0.5f * x));
    return fmaf(0.5f, t, 0.5f);
}
__device__ __forceinline__ uint32_t pack_h2(float lo, float hi) {
    uint32_t r;
    asm("cvt.rn.f16x2.f32 %0, %1, %2;" : "=r"(r) : "f"(hi), "f"(lo));  // %1 -> high half
    return r;
}
__device__ __forceinline__ void mma_f16(float c[4], const uint32_t a[4], uint32_t b0, uint32_t b1) {
    asm volatile(
        "mma.sync.aligned.m16n8k16.row.col.f32.f16.f16.f32 "
        "{%0,%1,%2,%3}, {%4,%5,%6,%7}, {%8,%9}, {%0,%1,%2,%3};"
        : "+f"(c[0]), "+f"(c[1]), "+f"(c[2]), "+f"(c[3])
        : "r"(a[0]), "r"(a[1]), "r"(a[2]), "r"(a[3]), "r"(b0), "r"(b1));
}

// ============================================================================
// Prep: batch-invariant fragment packing (runs once per launch; ~60 KB writes)
// ============================================================================
__global__ __launch_bounds__(NTHREADS)
void prep_kernel(const float* __restrict__ W1, const float* __restrict__ W2)
{
    const int idx = blockIdx.x * NTHREADS + threadIdx.x;
    const int nth = gridDim.x * NTHREADS;

    for (int fp = idx; fp < 1280; fp += nth) {
        int kt = fp / 320, rem = fp - kt * 320;
        int j = rem >> 5, l5 = rem & 31;
        int gg = l5 >> 2, tt = l5 & 3;
        int n = j * 8 + gg;
        int k0 = kt * 16 + tt * 2;
        float4 bc, d;
        bc.x = W1[(64 + k0    ) * H1 + n] - W1[(128 + k0    ) * H1 + n];
        bc.y = W1[(64 + k0 + 1) * H1 + n] - W1[(128 + k0 + 1) * H1 + n];
        bc.z = W1[(64 + k0 + 8) * H1 + n] - W1[(128 + k0 + 8) * H1 + n];
        bc.w = W1[(64 + k0 + 9) * H1 + n] - W1[(128 + k0 + 9) * H1 + n];
        d.x  = W1[(192 + k0    ) * H1 + n];
        d.y  = W1[(192 + k0 + 1) * H1 + n];
        d.z  = W1[(192 + k0 + 8) * H1 + n];
        d.w  = W1[(192 + k0 + 9) * H1 + n];
        g_bc4[fp] = bc;
        g_d4[fp]  = d;
    }
    for (int fp = idx; fp < 800; fp += nth) {
        int kt = fp / 160, rem = fp - kt * 160;
        int j2 = rem >> 5, l5 = rem & 31;
        int gg = l5 >> 2, tt = l5 & 3;
        int n = j2 * 8 + gg;
        int k0 = kt * 16 + tt * 2;
        uint2 h;
        h.x = pack_h2(W2[k0 * H2 + n],       W2[(k0 + 1) * H2 + n]);
        h.y = pack_h2(W2[(k0 + 8) * H2 + n], W2[(k0 + 9) * H2 + n]);
        g_w2f[fp] = h;
    }
    for (int i = idx; i < E_DIM * H1; i += nth)
        g_ac[i] = W1[i] + W1[128 * H1 + i];
}

// ============================================================================
// Fused kernel, fp16 tensor-core MLP. One CTA per batch, 4 CTAs/SM (64 regs).
// GEMM1 j-dim split 6/4 so acc1 is consumed incrementally by GEMM2.
// ============================================================================
__global__ __launch_bounds__(NTHREADS, 4)
void fused_kernel(const float* __restrict__ query,
                  const float* __restrict__ facts,
                  const int*   __restrict__ mask,
                  const float* __restrict__ b1,
                  const float* __restrict__ b2,
                  const float* __restrict__ W3,
                  float* __restrict__ out)
{
    extern __shared__ float sm[];
    uint32_t* fshh = (uint32_t*)sm;            // [208][36] half2 facts tile
    uint32_t* wfr  = fshh + ROWS * FH;         // [1280] uint2 = 2560 u32 (wefft f16 frags)
    uint32_t* w2fr = wfr + 2560;               // [800] uint2 = 1600 u32 (W2 f16 frags)
    float* c1sh    = (float*)(w2fr + 1600);    // [80]
    float* b2sh    = c1sh + H1;                // [40]
    float* w3sh    = b2sh + H2;                // [40]
    float* scoresh = w3sh + H2;                // [208]
    float* red     = scoresh + ROWS;           // [16]
    float* attnsh  = red + 16;                 // [208]
    float* outred  = attnsh + ROWS;            // [512]
    float* qsh     = outred + 512;             // [64]

    const int b    = blockIdx.x;
    const int tid  = threadIdx.x;
    const int w    = tid >> 5;
    const int lane = tid & 31;
    const int g    = lane >> 2;
    const int tg   = lane & 3;

    // ---------------- staging: facts -> f16 tile ----------------
    {
        const float4* fb = (const float4*)(facts + (size_t)b * T_LEN * E_DIM);
        for (int i = tid; i < T_LEN * 16; i += NTHREADS) {
            int t = i >> 4, e4 = i & 15;
            float4 v = fb[i];
            uint2 h;
            h.x = pack_h2(v.x, v.y);
            h.y = pack_h2(v.z, v.w);
            *(uint2*)&fshh[t * FH + e4 * 2] = h;
        }
        // zero pad rows [200,208): 8 rows * 18 uint2
        for (int i = tid; i < 144; i += NTHREADS) {
            int t = T_LEN + i / 18, c = i % 18;
            *(uint2*)&fshh[t * FH + c * 2] = make_uint2(0u, 0u);
        }
    }
    int mbit = (tid < T_LEN) ? mask[(size_t)b * T_LEN + tid] : 0;
    if (tid < E_DIM) qsh[tid] = query[(size_t)b * E_DIM + tid];
    if (tid < H2)    { b2sh[tid] = b2[tid]; w3sh[tid] = W3[tid]; }
    // W2 fragment copy: pure vector loads
    {
        const uint4* src = (const uint4*)g_w2f;
        uint4* dst = (uint4*)w2fr;
        for (int i = tid; i < 400; i += NTHREADS) dst[i] = src[i];
    }
    __syncthreads();    // qsh ready

    // ---------------- per-batch wefft fragments from precomputed BC/D ----------
    for (int fp = tid; fp < 1280; fp += NTHREADS) {
        int k0 = (fp / 320) * 16 + (fp & 3) * 2;
        float4 bc = g_bc4[fp];
        float4 d  = g_d4[fp];
        float q0 = qsh[k0], q1 = qsh[k0 + 1], q8 = qsh[k0 + 8], q9 = qsh[k0 + 9];
        uint2 h;
        h.x = pack_h2(fmaf(q0, d.x, bc.x), fmaf(q1, d.y, bc.y));
        h.y = pack_h2(fmaf(q8, d.z, bc.z), fmaf(q9, d.w, bc.w));
        *(uint2*)&wfr[fp * 2] = h;
    }
    // c1 = b1 + q@(A+C)
    if (tid < H1) {
        float acc = b1[tid];
        #pragma unroll 8
        for (int e = 0; e < E_DIM; e++)
            acc += qsh[e] * g_ac[e * H1 + tid];
        c1sh[tid] = acc;
    }
    __syncthreads();

    // ---------------- per-stripe MLP (warp w handles stripes w, w+8) ------------
    for (int s = w; s < NSTRIPES; s += 8) {
        const int r0 = s * 16;

        float acc2[5][4];
        #pragma unroll
        for (int j = 0; j < 5; j++)
            #pragma unroll
            for (int q = 0; q < 4; q++) acc2[j][q] = 0.0f;

        // ===== half 1: GEMM1 j in [0,6), then GEMM2 kt2 in {0,1,2} =====
        {
            float acc1[6][4];
            #pragma unroll
            for (int j = 0; j < 6; j++)
                #pragma unroll
                for (int q = 0; q < 4; q++) acc1[j][q] = 0.0f;

            #pragma unroll
            for (int kt = 0; kt < 4; kt++) {
                const int base = (r0 + g) * FH + kt * 8 + tg;
                uint32_t a[4];
                a[0] = fshh[base];
                a[1] = fshh[base + 8 * FH];
                a[2] = fshh[base + 4];
                a[3] = fshh[base + 8 * FH + 4];
                const uint2* wp = (const uint2*)wfr + kt * 320 + lane;
                #pragma unroll
                for (int j = 0; j < 6; j++) {
                    uint2 bw = wp[j * 32];
                    mma_f16(acc1[j], a, bw.x, bw.y);
                }
            }
            #pragma unroll
            for (int kt2 = 0; kt2 < 3; kt2++) {
                const int ja = 2 * kt2, jb = ja + 1;
                const float ca0 = c1sh[8 * ja + 2 * tg], ca1 = c1sh[8 * ja + 2 * tg + 1];
                const float cb0 = c1sh[8 * jb + 2 * tg], cb1 = c1sh[8 * jb + 2 * tg + 1];
                uint32_t a[4];
                a[0] = pack_h2(sigm(acc1[ja][0] + ca0), sigm(acc1[ja][1] + ca1));
                a[1] = pack_h2(sigm(acc1[ja][2] + ca0), sigm(acc1[ja][3] + ca1));
                a[2] = pack_h2(sigm(acc1[jb][0] + cb0), sigm(acc1[jb][1] + cb1));
                a[3] = pack_h2(sigm(acc1[jb][2] + cb0), sigm(acc1[jb][3] + cb1));
                const uint2* wp2 = (const uint2*)w2fr + kt2 * 160 + lane;
                #pragma unroll
                for (int j2 = 0; j2 < 5; j2++) {
                    uint2 bw = wp2[j2 * 32];
                    mma_f16(acc2[j2], a, bw.x, bw.y);
                }
            }
        }

        // ===== half 2: GEMM1 j in [6,10), then GEMM2 kt2 in {3,4} =====
        {
            float acc1[4][4];
            #pragma unroll
            for (int j = 0; j < 4; j++)
                #pragma unroll
                for (int q = 0; q < 4; q++) acc1[j][q] = 0.0f;

            #pragma unroll
            for (int kt = 0; kt < 4; kt++) {
                const int base = (r0 + g) * FH + kt * 8 + tg;
                uint32_t a[4];
                a[0] = fshh[base];
                a[1] = fshh[base + 8 * FH];
                a[2] = fshh[base + 4];
                a[3] = fshh[base + 8 * FH + 4];
                const uint2* wp = (const uint2*)wfr + kt * 320 + lane;
                #pragma unroll
                for (int j = 0; j < 4; j++) {
                    uint2 bw = wp[(6 + j) * 32];
                    mma_f16(acc1[j], a, bw.x, bw.y);
                }
            }
            #pragma unroll
            for (int kt2 = 3; kt2 < 5; kt2++) {
                const int ja = 2 * kt2, jb = ja + 1;       // global 6..9
                const int la = ja - 6, lb = jb - 6;        // local 0..3
                const float ca0 = c1sh[8 * ja + 2 * tg], ca1 = c1sh[8 * ja + 2 * tg + 1];
                const float cb0 = c1sh[8 * jb + 2 * tg], cb1 = c1sh[8 * jb + 2 * tg + 1];
                uint32_t a[4];
                a[0] = pack_h2(sigm(acc1[la][0] + ca0), sigm(acc1[la][1] + ca1));
                a[1] = pack_h2(sigm(acc1[la][2] + ca0), sigm(acc1[la][3] + ca1));
                a[2] = pack_h2(sigm(acc1[lb][0] + cb0), sigm(acc1[lb][1] + cb1));
                a[3] = pack_h2(sigm(acc1[lb][2] + cb0), sigm(acc1[lb][3] + cb1));
                const uint2* wp2 = (const uint2*)w2fr + kt2 * 160 + lane;
                #pragma unroll
                for (int j2 = 0; j2 < 5; j2++) {
                    uint2 bw = wp2[j2 * 32];
                    mma_f16(acc2[j2], a, bw.x, bw.y);
                }
            }
        }

        // epilogue: sigmoid, dot W3, quad-reduce, scores -> smem
        float s_lo = 0.0f, s_hi = 0.0f;
        #pragma unroll
        for (int j = 0; j < 5; j++) {
            const int n0 = j * 8 + 2 * tg;
            float bb0 = b2sh[n0], bb1 = b2sh[n0 + 1];
            float w30 = w3sh[n0], w31 = w3sh[n0 + 1];
            s_lo += sigm(acc2[j][0] + bb0) * w30 + sigm(acc2[j][1] + bb1) * w31;
            s_hi += sigm(acc2[j][2] + bb0) * w30 + sigm(acc2[j][3] + bb1) * w31;
        }
        s_lo += __shfl_xor_sync(0xFFFFFFFF, s_lo, 1);
        s_lo += __shfl_xor_sync(0xFFFFFFFF, s_lo, 2);
        s_hi += __shfl_xor_sync(0xFFFFFFFF, s_hi, 1);
        s_hi += __shfl_xor_sync(0xFFFFFFFF, s_hi, 2);

        if (tg == 0) {   // b3 omitted: constant shift cancels in softmax
            scoresh[r0 + g]     = s_lo;
            scoresh[r0 + g + 8] = s_hi;
        }
    }
    __syncthreads();

    // ---------------- masked softmax over T (warp-shuffle reductions) ----------
    const float PADV = -4294967295.0f;   // -2^32 + 1
    float v = (tid < T_LEN) ? ((mbit == 1) ? scoresh[tid] : PADV) : -INFINITY;

    float m = v;
    #pragma unroll
    for (int off = 16; off > 0; off >>= 1)
        m = fmaxf(m, __shfl_xor_sync(0xFFFFFFFF, m, off));
    if (lane == 0) red[w] = m;
    __syncthreads();
    float mmax = red[0];
    #pragma unroll
    for (int i = 1; i < 8; i++) mmax = fmaxf(mmax, red[i]);

    float p = (tid < T_LEN) ? __expf(v - mmax) : 0.0f;
    float ssum = p;
    #pragma unroll
    for (int off = 16; off > 0; off >>= 1)
        ssum += __shfl_xor_sync(0xFFFFFFFF, ssum, off);
    if (lane == 0) red[8 + w] = ssum;
    __syncthreads();
    float tot = red[8];
    #pragma unroll
    for (int i = 9; i < 16; i++) tot += red[i];
    float inv = 1.0f / tot;
    if (tid < ROWS) attnsh[tid] = p * inv;    // rows >= T_LEN get 0
    __syncthreads();

    // ---------------- out[b] = attn @ facts (f16 tile, fp32 accumulate) --------
    {
        const int e2 = tid & 31;       // half2 column
        const int c  = tid >> 5;       // 8 chunks of 26 rows
        float ax = 0.0f, ay = 0.0f;
        const int t0 = c * 26;
        #pragma unroll 13
        for (int t = t0; t < t0 + 26; t++) {
            uint32_t h = fshh[t * FH + e2];
            float2 f = __half22float2(*(__half2*)&h);
            float at = attnsh[t];
            ax = fmaf(at, f.x, ax);
            ay = fmaf(at, f.y, ay);
        }
        outred[c * 64 + 2 * e2]     = ax;
        outred[c * 64 + 2 * e2 + 1] = ay;
    }
    __syncthreads();
    if (tid < E_DIM) {
        float o = 0.0f;
        #pragma unroll
        for (int c = 0; c < 8; c++) o += outred[c * 64 + tid];
        out[(size_t)b * E_DIM + tid] = o;
    }
}

// ============================================================================
// launch
// ============================================================================
static inline size_t fused_smem_bytes() {
    size_t u32s = (size_t)ROWS * FH + 2560 + 1600;                 // f16/frag areas
    size_t flts = H1 + H2 + H2 + ROWS + 16 + ROWS + 512 + E_DIM;   // fp32 areas
    return (u32s + flts) * 4;
}

extern "C" void kernel_launch(void* const* d_in, const int* in_sizes, int n_in,
                              void* d_out, int out_size)
{
    const float* query = (const float*)d_in[0];
    const float* facts = (const float*)d_in[1];
    const int*   mask  = (const int*)  d_in[2];
    const float* W1    = (const float*)d_in[3];
    const float* b1    = (const float*)d_in[4];
    const float* W2    = (const float*)d_in[5];
    const float* b2    = (const float*)d_in[6];
    const float* W3    = (const float*)d_in[7];
    float* out = (float*)d_out;

    const int B = in_sizes[0] / E_DIM;

    static bool configured = false;
    if (!configured) {
        cudaFuncSetAttribute(fused_kernel,
                             cudaFuncAttributeMaxDynamicSharedMemorySize,
                             (int)fused_smem_bytes());
        configured = true;
    }

    prep_kernel<<<16, NTHREADS>>>(W1, W2);
    fused_kernel<<<B, NTHREADS, fused_smem_bytes()>>>(query, facts, mask,
                                                      b1, b2, W3, out);
}